// round 11
// baseline (speedup 1.0000x reference)
#include <cuda_runtime.h>

#define BATCH  128
#define TSTEPS 512
#define FEAT   64
#define UN1    256
#define UN2    128

// packed fp32x2 FMA (Blackwell): two fp32 FMAs per instruction
#define FMA2(acc, a, b) \
  asm("fma.rn.f32x2 %0, %1, %2, %0;" : "+l"(acc) : "l"(a), "l"(b))
#define SPLAT2(dst, x) \
  asm("mov.b64 %0, {%1, %1};" : "=l"(dst) : "r"(__float_as_uint(x)))

#define CP_ASYNC16(saddr, gaddr) \
  asm volatile("cp.async.cg.shared.global [%0], [%1], 16;" :: "r"(saddr), "l"(gaddr))
#define CP_COMMIT() asm volatile("cp.async.commit_group;")
#define CP_WAIT0()  asm volatile("cp.async.wait_group 0;")

// ---------------- scratch ------------------------------------------------------
__device__ float g_hseq1[(size_t)(TSTEPS + 1) * UN1 * BATCH];  // [t][u][b], slot0 = 0
__device__ float g_hseq2[(size_t)(TSTEPS + 1) * UN2 * BATCH];  // [t][u][b], slot0 = 0
__device__ unsigned g_bar[4], g_exit[4];                       // per batch-group

// ---------------- fused persistent 2-layer LSTM --------------------------------
// 128 CTAs = 4 bg (32 batches) x 32 ug; 512 threads = 16 warps.
// Warp q (=wid) owns k-slice q; covers ALL 32 L1 cols + 16 L2 cols of the tile.
// 16 partial slices reduced in the epilogues.
__global__ void __launch_bounds__(512)
lstm_fused(const float* __restrict__ x,
           const float* __restrict__ W1, const float* __restrict__ U1m,
           const float* __restrict__ b1,
           const float* __restrict__ W2, const float* __restrict__ U2m,
           const float* __restrict__ b2,
           float* __restrict__ out_last) {
  constexpr int SHS  = 36;   // sH / sH2e row stride
  constexpr int SXS  = 33;   // sX row stride
  constexpr int ZPS  = 33;   // sZp1: [q*32+col][bl]
  constexpr int ZP2S = 33;   // sZp2: [q*16+col][bl]

  extern __shared__ float smem[];
  float* sU1  = smem;                   // [256][32]
  float* sW1x = sU1 + 256 * 32;         // [64][32]
  float* sUW2 = sW1x + 64 * 32;         // [384][16]  W2 | U2
  float* sH   = sUW2 + 384 * 16;        // [256][SHS] h1_{t-1} [k][b]
  float* sH2e = sH + 256 * SHS;         // [128][SHS] h2_{t-2} [k][b]
  float* sX   = sH2e + 128 * SHS;       // [64][SXS]  x_t [f][b]
  float* sZp1 = sX + 64 * SXS;          // [16*32][ZPS]
  float* sZp2 = sZp1 + 16 * 32 * ZPS;   // [16*16][ZP2S]

  const int tid = threadIdx.x;
  const int bg  = blockIdx.x >> 5;
  const int ug  = blockIdx.x & 31;
  const int b0  = bg * 32;
  unsigned* bar   = &g_bar[bg];
  unsigned* exitc = &g_exit[bg];

  // ---- weight slices (once) ----
  for (int i = tid; i < 256 * 32; i += 512) {
    int k = i >> 5, cc = i & 31;
    sU1[i] = U1m[(size_t)k * 1024 + (cc >> 3) * 256 + ug * 8 + (cc & 7)];
  }
  for (int i = tid; i < 64 * 32; i += 512) {
    int k = i >> 5, cc = i & 31;
    sW1x[i] = W1[(size_t)k * 1024 + (cc >> 3) * 256 + ug * 8 + (cc & 7)];
  }
  for (int i = tid; i < 384 * 16; i += 512) {
    int k = i >> 4, c = i & 15;
    int col = (c >> 2) * 128 + ug * 4 + (c & 3);
    sUW2[i] = (k < 256) ? W2[(size_t)k * 512 + col]
                        : U2m[(size_t)(k - 256) * 512 + col];
  }

  // ---- thread mappings (compute) ----
  const int q  = tid >> 5;           // warp = k-slice 0..15
  const int li = tid & 31;
  const int tm = li >> 2;            // rows 4*tm..+3
  const int tn = li & 3;             // gate

  // epilogue mappings
  const int uu  = tid >> 5;          // L1 unit (valid for tid<256)
  const int bl  = tid & 31;
  const int b_g = b0 + bl;
  const int u_g = ug * 8 + (uu & 7);
  const int uu2  = (tid >> 5) & 3;   // L2 unit (tid<128)
  const int u_g2 = ug * 4 + uu2;

  float c1 = 0.f, c2 = 0.f;
  float b1g[4], b2g[4];
  if (tid < 256) {
#pragma unroll
    for (int g = 0; g < 4; g++) b1g[g] = b1[g * 256 + u_g];
  }
  if (tid < 128) {
#pragma unroll
    for (int g = 0; g < 4; g++) b2g[g] = b2[g * 128 + u_g2];
  }

  const unsigned sH_u   = (unsigned)__cvta_generic_to_shared(sH);
  const unsigned sH2e_u = (unsigned)__cvta_generic_to_shared(sH2e);

  // ---- init h_{-1}, first arrive, stage sX(t=0) ----
  if (tid < 256) g_hseq1[(size_t)u_g * BATCH + b_g] = 0.f;
  if (tid < 128) g_hseq2[(size_t)u_g2 * BATCH + b_g] = 0.f;
  __syncthreads();
  if (tid == 0)
    asm volatile("red.release.gpu.global.add.u32 [%0], %1;" :: "l"(bar), "r"(1u));
  {
    int bb = tid >> 4, f4 = (tid & 15) << 2;
    float4 v = *(const float4*)(x + (size_t)(b0 + bb) * TSTEPS * FEAT + f4);
    sX[(f4 + 0) * SXS + bb] = v.x;
    sX[(f4 + 1) * SXS + bb] = v.y;
    sX[(f4 + 2) * SXS + bb] = v.z;
    sX[(f4 + 3) * SXS + bb] = v.w;
  }

  for (int t = 0; t <= TSTEPS; t++) {
    // ---- wait: h1_{t-1} and h2_{t-2} sealed ----
    if (tid == 0) {
      const unsigned tgt = (unsigned)(t + 1) * 32u;
      unsigned v;
      do {
        asm volatile("ld.relaxed.gpu.global.u32 %0, [%1];" : "=r"(v) : "l"(bar));
      } while (v < tgt);
      asm volatile("ld.acquire.gpu.global.u32 %0, [%1];" : "=r"(v) : "l"(bar));
    }
    __syncthreads();                                   // S1

    // ---- issue async staging: sH = h1_{t-1}; sH2e = h2_{t-2} ----
    {
      const float* hp = g_hseq1 + (size_t)t * UN1 * BATCH + b0;
#pragma unroll
      for (int j = 0; j < 4; j++) {
        int i = tid + j * 512;
        int k = i >> 3, b4 = (i & 7) << 2;
        CP_ASYNC16(sH_u + (unsigned)(k * SHS + b4) * 4u,
                   hp + (size_t)k * BATCH + b4);
      }
    }
    if (t >= 1) {
      const float* hp = g_hseq2 + (size_t)(t - 1) * UN2 * BATCH + b0;
#pragma unroll
      for (int j = 0; j < 2; j++) {
        int i = tid + j * 512;
        int k = i >> 3, b4 = (i & 7) << 2;
        CP_ASYNC16(sH2e_u + (unsigned)(k * SHS + b4) * 4u,
                   hp + (size_t)k * BATCH + b4);
      }
    }
    CP_COMMIT();

    // ---- L1 x-part while copies fly (k-slice of 4) ----
    unsigned long long acc[4][4];   // 4 rows x 8 L1 cols
    unsigned long long acc2[4][2];  // 4 rows x 4 L2 cols
#pragma unroll
    for (int r = 0; r < 4; r++) {
#pragma unroll
      for (int c = 0; c < 4; c++) acc[r][c] = 0ull;
      acc2[r][0] = 0ull; acc2[r][1] = 0ull;
    }
    if (t < TSTEPS) {
#pragma unroll
      for (int kk = 0; kk < 4; kk++) {
        int k = q * 4 + kk;
        const float* ap = sX + k * SXS + 4 * tm;
        float a0 = ap[0], a1 = ap[1], a2 = ap[2], a3 = ap[3];
        ulonglong2 uA = *(const ulonglong2*)(sW1x + k * 32 + 8 * tn);
        ulonglong2 uB = *(const ulonglong2*)(sW1x + k * 32 + 8 * tn + 4);
        unsigned long long s0, s1, s2, s3;
        SPLAT2(s0, a0); SPLAT2(s1, a1); SPLAT2(s2, a2); SPLAT2(s3, a3);
        FMA2(acc[0][0], s0, uA.x); FMA2(acc[0][1], s0, uA.y);
        FMA2(acc[0][2], s0, uB.x); FMA2(acc[0][3], s0, uB.y);
        FMA2(acc[1][0], s1, uA.x); FMA2(acc[1][1], s1, uA.y);
        FMA2(acc[1][2], s1, uB.x); FMA2(acc[1][3], s1, uB.y);
        FMA2(acc[2][0], s2, uA.x); FMA2(acc[2][1], s2, uA.y);
        FMA2(acc[2][2], s2, uB.x); FMA2(acc[2][3], s2, uB.y);
        FMA2(acc[3][0], s3, uA.x); FMA2(acc[3][1], s3, uA.y);
        FMA2(acc[3][2], s3, uB.x); FMA2(acc[3][3], s3, uB.y);
      }
    }
    CP_WAIT0();
    __syncthreads();                                   // S2

    // ---- MERGED loop over sH (k-slice of 16): L1 U1-part + L2 W2-part ----
#pragma unroll 4
    for (int kk = 0; kk < 16; kk++) {
      int k = q * 16 + kk;
      float4 a = *(const float4*)(sH + k * SHS + 4 * tm);
      ulonglong2 uA = *(const ulonglong2*)(sU1 + k * 32 + 8 * tn);
      ulonglong2 uB = *(const ulonglong2*)(sU1 + k * 32 + 8 * tn + 4);
      ulonglong2 u2 = *(const ulonglong2*)(sUW2 + k * 16 + 4 * tn);
      unsigned long long s0, s1, s2, s3;
      SPLAT2(s0, a.x); SPLAT2(s1, a.y); SPLAT2(s2, a.z); SPLAT2(s3, a.w);
      FMA2(acc[0][0], s0, uA.x); FMA2(acc[0][1], s0, uA.y);
      FMA2(acc[0][2], s0, uB.x); FMA2(acc[0][3], s0, uB.y);
      FMA2(acc2[0][0], s0, u2.x); FMA2(acc2[0][1], s0, u2.y);
      FMA2(acc[1][0], s1, uA.x); FMA2(acc[1][1], s1, uA.y);
      FMA2(acc[1][2], s1, uB.x); FMA2(acc[1][3], s1, uB.y);
      FMA2(acc2[1][0], s1, u2.x); FMA2(acc2[1][1], s1, u2.y);
      FMA2(acc[2][0], s2, uA.x); FMA2(acc[2][1], s2, uA.y);
      FMA2(acc[2][2], s2, uB.x); FMA2(acc[2][3], s2, uB.y);
      FMA2(acc2[2][0], s2, u2.x); FMA2(acc2[2][1], s2, u2.y);
      FMA2(acc[3][0], s3, uA.x); FMA2(acc[3][1], s3, uA.y);
      FMA2(acc[3][2], s3, uB.x); FMA2(acc[3][3], s3, uB.y);
      FMA2(acc2[3][0], s3, u2.x); FMA2(acc2[3][1], s3, u2.y);
    }

    // ---- L2 U2-part over sH2e (k-slice of 8) ----
#pragma unroll 8
    for (int kk = 0; kk < 8; kk++) {
      int k = q * 8 + kk;
      float4 a = *(const float4*)(sH2e + k * SHS + 4 * tm);
      ulonglong2 u2 = *(const ulonglong2*)(sUW2 + (256 + k) * 16 + 4 * tn);
      unsigned long long s0, s1, s2, s3;
      SPLAT2(s0, a.x); SPLAT2(s1, a.y); SPLAT2(s2, a.z); SPLAT2(s3, a.w);
      FMA2(acc2[0][0], s0, u2.x); FMA2(acc2[0][1], s0, u2.y);
      FMA2(acc2[1][0], s1, u2.x); FMA2(acc2[1][1], s1, u2.y);
      FMA2(acc2[2][0], s2, u2.x); FMA2(acc2[2][1], s2, u2.y);
      FMA2(acc2[3][0], s3, u2.x); FMA2(acc2[3][1], s3, u2.y);
    }

    // ---- partial stores ([col][bl] layout) ----
#pragma unroll
    for (int r = 0; r < 4; r++) {
#pragma unroll
      for (int p = 0; p < 4; p++) {
        float lo = __uint_as_float((unsigned)(acc[r][p] & 0xffffffffu));
        float hi = __uint_as_float((unsigned)(acc[r][p] >> 32));
        sZp1[(q * 32 + 8 * tn + 2 * p)     * ZPS + 4 * tm + r] = lo;
        sZp1[(q * 32 + 8 * tn + 2 * p + 1) * ZPS + 4 * tm + r] = hi;
      }
#pragma unroll
      for (int p = 0; p < 2; p++) {
        float lo = __uint_as_float((unsigned)(acc2[r][p] & 0xffffffffu));
        float hi = __uint_as_float((unsigned)(acc2[r][p] >> 32));
        sZp2[(q * 16 + 4 * tn + 2 * p)     * ZP2S + 4 * tm + r] = lo;
        sZp2[(q * 16 + 4 * tn + 2 * p + 1) * ZP2S + 4 * tm + r] = hi;
      }
    }
    __syncthreads();                                   // S3

    // ---- L1 epilogue (threads 0..255): reduce 16 partials ----
    if (t < TSTEPS && tid < 256) {
      float z[4];
#pragma unroll
      for (int g = 0; g < 4; g++) {
        float s = b1g[g];
#pragma unroll
        for (int q2 = 0; q2 < 16; q2++)
          s += sZp1[(q2 * 32 + g * 8 + uu) * ZPS + bl];
        z[g] = s;
      }
      float ig = 1.f / (1.f + __expf(-z[0]));
      float fg = 1.f / (1.f + __expf(-z[1]));
      float gg = fmaxf(z[2], 0.f);
      float og = 1.f / (1.f + __expf(-z[3]));
      c1 = fg * c1 + ig * gg;
      float h = og * fmaxf(c1, 0.f);
      g_hseq1[(size_t)(t + 1) * UN1 * BATCH + (size_t)u_g * BATCH + b_g] = h;
    }
    // ---- L2 epilogue (threads 0..127; computes h2_{t-1}) ----
    if (t >= 1 && tid < 128) {
      float z[4];
#pragma unroll
      for (int g = 0; g < 4; g++) {
        float s = b2g[g];
#pragma unroll
        for (int q2 = 0; q2 < 16; q2++)
          s += sZp2[(q2 * 16 + g * 4 + uu2) * ZP2S + bl];
        z[g] = s;
      }
      float ig = 1.f / (1.f + __expf(-z[0]));
      float fg = 1.f / (1.f + __expf(-z[1]));
      float gg = fmaxf(z[2], 0.f);
      float og = 1.f / (1.f + __expf(-z[3]));
      c2 = fg * c2 + ig * gg;
      float h = og * fmaxf(c2, 0.f);
      if (t < TSTEPS)
        g_hseq2[(size_t)t * UN2 * BATCH + (size_t)u_g2 * BATCH + b_g] = h;
      else
        out_last[b_g * UN2 + u_g2] = h;
    }
    __syncthreads();                                   // S4 (h stores sealed)

    // ---- arrive, then stage sX for t+1 in the barrier shadow ----
    if (tid == 0 && t < TSTEPS)
      asm volatile("red.release.gpu.global.add.u32 [%0], %1;" :: "l"(bar), "r"(1u));
    if (t + 1 < TSTEPS) {
      int bb = tid >> 4, f4 = (tid & 15) << 2;
      float4 v = *(const float4*)(x + (size_t)(b0 + bb) * TSTEPS * FEAT
                                    + (size_t)(t + 1) * FEAT + f4);
      sX[(f4 + 0) * SXS + bb] = v.x;
      sX[(f4 + 1) * SXS + bb] = v.y;
      sX[(f4 + 2) * SXS + bb] = v.z;
      sX[(f4 + 3) * SXS + bb] = v.w;
    }
  }

  // ---- exit: last CTA of bg resets counters for next graph replay ----
  __syncthreads();
  if (tid == 0) {
    __threadfence();
    if (atomicAdd(exitc, 1u) + 1u == 32u) {
      *bar = 0u;
      *exitc = 0u;
    }
  }
}

// ---------------- launch --------------------------------------------------------
extern "C" void kernel_launch(void* const* d_in, const int* in_sizes, int n_in,
                              void* d_out, int out_size) {
  const float* x   = (const float*)d_in[0];
  const float* W1  = (const float*)d_in[1];
  const float* U1m = (const float*)d_in[2];
  const float* b1  = (const float*)d_in[3];
  const float* W2  = (const float*)d_in[4];
  const float* U2m = (const float*)d_in[5];
  const float* b2  = (const float*)d_in[6];
  float* out = (float*)d_out;

  constexpr int SMEM = (256 * 32 + 64 * 32 + 384 * 16 + 256 * 36 + 128 * 36 +
                        64 * 33 + 16 * 32 * 33 + 16 * 16 * 33) * 4;  // 230656 B
  cudaFuncSetAttribute(lstm_fused, cudaFuncAttributeMaxDynamicSharedMemorySize, SMEM);

  lstm_fused<<<128, 512, SMEM>>>(x, W1, U1m, b1, W2, U2m, b2, out);
}

// round 13
// speedup vs baseline: 1.1157x; 1.1157x over previous
#include <cuda_runtime.h>

#define BATCH  128
#define TSTEPS 512
#define FEAT   64
#define UN1    256
#define UN2    128

// packed fp32x2 FMA (Blackwell): two fp32 FMAs per instruction
#define FMA2(acc, a, b) \
  asm("fma.rn.f32x2 %0, %1, %2, %0;" : "+l"(acc) : "l"(a), "l"(b))
#define SPLAT2(dst, x) \
  asm("mov.b64 %0, {%1, %1};" : "=l"(dst) : "r"(__float_as_uint(x)))

#define CP_ASYNC16(saddr, gaddr) \
  asm volatile("cp.async.cg.shared.global [%0], [%1], 16;" :: "r"(saddr), "l"(gaddr))
#define CP_COMMIT() asm volatile("cp.async.commit_group;")
#define CP_WAIT0()  asm volatile("cp.async.wait_group 0;")

// ---------------- scratch ------------------------------------------------------
__device__ float g_xw1[(size_t)BATCH * TSTEPS * 4 * UN1];      // [b][t][1024] = x@W1+b1
__device__ float g_hseq1[(size_t)(TSTEPS + 1) * UN1 * BATCH];  // [t][u][b]
__device__ float g_hseq2[(size_t)(TSTEPS + 1) * UN2 * BATCH];  // [t][u][b]
__device__ unsigned g_bar[4], g_exit[4];                       // per batch-group

// ---------------- feed-forward GEMM: g_xw1 = x @ W1 + b1 -----------------------
__global__ void __launch_bounds__(256)
gemm_xw1(const float* __restrict__ Ain, const float* __restrict__ W,
         const float* __restrict__ bias) {
  constexpr int N = 4 * UN1, K = FEAT;
  __shared__ float sA[64][68];
  __shared__ float sW[64][68];
  const int n0 = blockIdx.x * 64;
  const int m0 = blockIdx.y * 64;
  const int tid = threadIdx.x;
  const int ty = tid >> 4, tx = tid & 15;

  unsigned long long acc[4][2];
#pragma unroll
  for (int r = 0; r < 4; r++) { acc[r][0] = 0ull; acc[r][1] = 0ull; }

  for (int kt = 0; kt < K; kt += 64) {
    for (int i = tid; i < 64 * 64; i += 256) {
      int r = i >> 6, c = i & 63;
      sA[c][r] = Ain[(size_t)(m0 + r) * K + kt + c];
      sW[r][c] = W[(size_t)(kt + r) * N + n0 + c];
    }
    __syncthreads();
#pragma unroll 8
    for (int k = 0; k < 64; k++) {
      float4 a = *(const float4*)&sA[k][ty * 4];
      ulonglong2 w2 = *(const ulonglong2*)&sW[k][tx * 4];
      unsigned long long s0, s1, s2, s3;
      SPLAT2(s0, a.x); SPLAT2(s1, a.y); SPLAT2(s2, a.z); SPLAT2(s3, a.w);
      FMA2(acc[0][0], s0, w2.x); FMA2(acc[0][1], s0, w2.y);
      FMA2(acc[1][0], s1, w2.x); FMA2(acc[1][1], s1, w2.y);
      FMA2(acc[2][0], s2, w2.x); FMA2(acc[2][1], s2, w2.y);
      FMA2(acc[3][0], s3, w2.x); FMA2(acc[3][1], s3, w2.y);
    }
    __syncthreads();
  }
  float4 bv = *(const float4*)&bias[n0 + tx * 4];
#pragma unroll
  for (int i = 0; i < 4; i++) {
    float4 o;
    o.x = __uint_as_float((unsigned)(acc[i][0] & 0xffffffffu)) + bv.x;
    o.y = __uint_as_float((unsigned)(acc[i][0] >> 32)) + bv.y;
    o.z = __uint_as_float((unsigned)(acc[i][1] & 0xffffffffu)) + bv.z;
    o.w = __uint_as_float((unsigned)(acc[i][1] >> 32)) + bv.w;
    *(float4*)&g_xw1[(size_t)(m0 + ty * 4 + i) * N + n0 + tx * 4] = o;
  }
}

// ---------------- fused persistent 2-layer LSTM --------------------------------
// 256 CTAs = 4 bg (32 batches) x 64 ug; 256 threads = 8 warps; 2 CTAs per SM.
// Per CTA: 16 L1 cols (4 gates x 4 units), 8 L2 cols (4 gates x 2 units).
// Warp q = k-slice. xw folded ONLY by warp 0 (counted once in the reduce).
__global__ void __launch_bounds__(256)
lstm_fused(const float* __restrict__ U1m, const float* __restrict__ b1,
           const float* __restrict__ W2, const float* __restrict__ U2m,
           const float* __restrict__ b2, float* __restrict__ out_last) {
  constexpr int SHS = 36;    // sH / sH2e row stride
  constexpr int ZPS = 33;    // partial stride

  extern __shared__ float smem[];
  float* sU1  = smem;                   // [256][16]
  float* sUW2 = sU1 + 256 * 16;         // [384][8]   W2 | U2
  float* sH   = sUW2 + 384 * 8;         // [256][SHS] h1_{t-1} [k][b]
  float* sH2e = sH + 256 * SHS;         // [128][SHS] h2_{t-2} [k][b]
  float* sZp1 = sH2e + 128 * SHS;       // [8*16][ZPS]
  float* sZp2 = sZp1 + 8 * 16 * ZPS;    // [8*8][ZPS]

  const int tid = threadIdx.x;
  const int bg  = blockIdx.x >> 6;      // 0..3
  const int ug  = blockIdx.x & 63;      // 0..63
  const int b0  = bg * 32;
  unsigned* bar   = &g_bar[bg];
  unsigned* exitc = &g_exit[bg];

  // ---- weight slices (once) ----
  for (int i = tid; i < 256 * 16; i += 256) {
    int k = i >> 4, c = i & 15;
    sU1[i] = U1m[(size_t)k * 1024 + (c >> 2) * 256 + ug * 4 + (c & 3)];
  }
  for (int i = tid; i < 384 * 8; i += 256) {
    int k = i >> 3, c = i & 7;
    int col = (c >> 1) * 128 + ug * 2 + (c & 1);
    sUW2[i] = (k < 256) ? W2[(size_t)k * 512 + col]
                        : U2m[(size_t)(k - 256) * 512 + col];
  }

  // ---- thread mappings (compute) ----
  const int q  = tid >> 5;           // warp = k-slice 0..7
  const int li = tid & 31;
  const int tm = li >> 2;            // rows 4*tm..+3
  const int tn = li & 3;             // gate

  // epilogue mappings: tid<128 -> L1 cell; 128<=tid<192 -> L2 cell
  const int bl  = tid & 31;
  const int b_g = b0 + bl;
  const int uu  = (tid >> 5) & 3;    // L1 unit idx (tid<128)
  const int u_g = ug * 4 + uu;
  const int lt  = tid - 128;
  const int bl2 = lt & 31;
  const int uu2 = (lt >> 5) & 1;     // L2 unit idx (tid in [128,192))
  const int u_g2 = ug * 2 + uu2;

  float c1 = 0.f, c2 = 0.f;
  float b1g[4], b2g[4];
  if (tid < 128) {
#pragma unroll
    for (int g = 0; g < 4; g++) b1g[g] = b1[g * 256 + u_g];
  }
  if (tid >= 128 && tid < 192) {
#pragma unroll
    for (int g = 0; g < 4; g++) b2g[g] = b2[g * 128 + u_g2];
  }

  const unsigned sH_u   = (unsigned)__cvta_generic_to_shared(sH);
  const unsigned sH2e_u = (unsigned)__cvta_generic_to_shared(sH2e);

  // ---- init h_{-1}, first arrive ----
  if (tid < 128) g_hseq1[(size_t)u_g * BATCH + b_g] = 0.f;
  if (tid >= 128 && tid < 192) g_hseq2[(size_t)u_g2 * BATCH + b0 + bl2] = 0.f;
  __syncthreads();
  if (tid == 0)
    asm volatile("red.release.gpu.global.add.u32 [%0], %1;" :: "l"(bar), "r"(1u));

  // xw tile base (warp 0 only): rows b0+4tm..+3; cols gate tn, units ug*4..+3
  const size_t xbase = (size_t)(b0 + 4 * tm) * TSTEPS * 1024
                     + (size_t)tn * 256 + (size_t)ug * 4;

  for (int t = 0; t <= TSTEPS; t++) {
    // ---- prefetch xw tile (warp 0 only; overlaps barrier wait) ----
    ulonglong2 xwv[4];
    if (q == 0 && t < TSTEPS) {
      const float* xp = g_xw1 + xbase + (size_t)t * 1024;
#pragma unroll
      for (int r = 0; r < 4; r++)
        xwv[r] = *(const ulonglong2*)(xp + (size_t)r * TSTEPS * 1024);
    }

    // ---- wait: h1_{t-1} and h2_{t-2} sealed ----
    if (tid == 0) {
      const unsigned tgt = (unsigned)(t + 1) * 64u;
      unsigned v;
      do {
        asm volatile("ld.relaxed.gpu.global.u32 %0, [%1];" : "=r"(v) : "l"(bar));
      } while (v < tgt);
      asm volatile("ld.acquire.gpu.global.u32 %0, [%1];" : "=r"(v) : "l"(bar));
    }
    __syncthreads();                                   // S1

    // ---- async staging: sH = h1_{t-1}; sH2e = h2_{t-2} ----
    {
      const float* hp = g_hseq1 + (size_t)t * UN1 * BATCH + b0;
#pragma unroll
      for (int j = 0; j < 8; j++) {
        int i = tid + j * 256;
        int k = i >> 3, b4 = (i & 7) << 2;
        CP_ASYNC16(sH_u + (unsigned)(k * SHS + b4) * 4u,
                   hp + (size_t)k * BATCH + b4);
      }
    }
    if (t >= 1) {
      const float* hp = g_hseq2 + (size_t)(t - 1) * UN2 * BATCH + b0;
#pragma unroll
      for (int j = 0; j < 4; j++) {
        int i = tid + j * 256;
        int k = i >> 3, b4 = (i & 7) << 2;
        CP_ASYNC16(sH2e_u + (unsigned)(k * SHS + b4) * 4u,
                   hp + (size_t)k * BATCH + b4);
      }
    }
    CP_COMMIT();

    // ---- init accs: ONLY warp 0 folds xw (counted once after reduce) ----
    unsigned long long acc[4][2];   // 4 rows x 4 L1 cols
    unsigned long long acc2[4];     // 4 rows x 2 L2 cols
    if (q == 0 && t < TSTEPS) {
#pragma unroll
      for (int r = 0; r < 4; r++) {
        acc[r][0] = xwv[r].x; acc[r][1] = xwv[r].y; acc2[r] = 0ull;
      }
    } else {
#pragma unroll
      for (int r = 0; r < 4; r++) { acc[r][0] = 0ull; acc[r][1] = 0ull; acc2[r] = 0ull; }
    }
    CP_WAIT0();
    __syncthreads();                                   // S2

    // ---- MERGED loop over sH (k-slice of 32): L1 U1-part + L2 W2-part ----
#pragma unroll 4
    for (int kk = 0; kk < 32; kk++) {
      int k = q * 32 + kk;
      float4 a = *(const float4*)(sH + k * SHS + 4 * tm);
      ulonglong2 uA = *(const ulonglong2*)(sU1 + k * 16 + 4 * tn);
      unsigned long long u2 = *(const unsigned long long*)(sUW2 + k * 8 + 2 * tn);
      unsigned long long s0, s1, s2, s3;
      SPLAT2(s0, a.x); SPLAT2(s1, a.y); SPLAT2(s2, a.z); SPLAT2(s3, a.w);
      FMA2(acc[0][0], s0, uA.x); FMA2(acc[0][1], s0, uA.y); FMA2(acc2[0], s0, u2);
      FMA2(acc[1][0], s1, uA.x); FMA2(acc[1][1], s1, uA.y); FMA2(acc2[1], s1, u2);
      FMA2(acc[2][0], s2, uA.x); FMA2(acc[2][1], s2, uA.y); FMA2(acc2[2], s2, u2);
      FMA2(acc[3][0], s3, uA.x); FMA2(acc[3][1], s3, uA.y); FMA2(acc2[3], s3, u2);
    }

    // ---- L2 U2-part over sH2e (k-slice of 16) ----
#pragma unroll 8
    for (int kk = 0; kk < 16; kk++) {
      int k = q * 16 + kk;
      float4 a = *(const float4*)(sH2e + k * SHS + 4 * tm);
      unsigned long long u2 = *(const unsigned long long*)(sUW2 + (256 + k) * 8 + 2 * tn);
      unsigned long long s0, s1, s2, s3;
      SPLAT2(s0, a.x); SPLAT2(s1, a.y); SPLAT2(s2, a.z); SPLAT2(s3, a.w);
      FMA2(acc2[0], s0, u2);
      FMA2(acc2[1], s1, u2);
      FMA2(acc2[2], s2, u2);
      FMA2(acc2[3], s3, u2);
    }

    // ---- partial stores ([col][bl] layout) ----
#pragma unroll
    for (int r = 0; r < 4; r++) {
#pragma unroll
      for (int p = 0; p < 2; p++) {
        float lo = __uint_as_float((unsigned)(acc[r][p] & 0xffffffffu));
        float hi = __uint_as_float((unsigned)(acc[r][p] >> 32));
        sZp1[(q * 16 + 4 * tn + 2 * p)     * ZPS + 4 * tm + r] = lo;
        sZp1[(q * 16 + 4 * tn + 2 * p + 1) * ZPS + 4 * tm + r] = hi;
      }
      {
        float lo = __uint_as_float((unsigned)(acc2[r] & 0xffffffffu));
        float hi = __uint_as_float((unsigned)(acc2[r] >> 32));
        sZp2[(q * 8 + 2 * tn)     * ZPS + 4 * tm + r] = lo;
        sZp2[(q * 8 + 2 * tn + 1) * ZPS + 4 * tm + r] = hi;
      }
    }
    __syncthreads();                                   // S3

    // ---- L1 epilogue (tid<128) ----
    if (t < TSTEPS && tid < 128) {
      float z[4];
#pragma unroll
      for (int g = 0; g < 4; g++) {
        float s = b1g[g];
#pragma unroll
        for (int q2 = 0; q2 < 8; q2++)
          s += sZp1[(q2 * 16 + g * 4 + uu) * ZPS + bl];
        z[g] = s;
      }
      float ig = 1.f / (1.f + __expf(-z[0]));
      float fg = 1.f / (1.f + __expf(-z[1]));
      float gg = fmaxf(z[2], 0.f);
      float og = 1.f / (1.f + __expf(-z[3]));
      c1 = fg * c1 + ig * gg;
      float h = og * fmaxf(c1, 0.f);
      g_hseq1[(size_t)(t + 1) * UN1 * BATCH + (size_t)u_g * BATCH + b_g] = h;
    }
    // ---- L2 epilogue (tid in [128,192); computes h2_{t-1}) ----
    if (t >= 1 && tid >= 128 && tid < 192) {
      float z[4];
#pragma unroll
      for (int g = 0; g < 4; g++) {
        float s = b2g[g];
#pragma unroll
        for (int q2 = 0; q2 < 8; q2++)
          s += sZp2[(q2 * 8 + g * 2 + uu2) * ZPS + bl2];
        z[g] = s;
      }
      float ig = 1.f / (1.f + __expf(-z[0]));
      float fg = 1.f / (1.f + __expf(-z[1]));
      float gg = fmaxf(z[2], 0.f);
      float og = 1.f / (1.f + __expf(-z[3]));
      c2 = fg * c2 + ig * gg;
      float h = og * fmaxf(c2, 0.f);
      if (t < TSTEPS)
        g_hseq2[(size_t)t * UN2 * BATCH + (size_t)u_g2 * BATCH + b0 + bl2] = h;
      else
        out_last[(b0 + bl2) * UN2 + u_g2] = h;
    }
    __syncthreads();                                   // S4 (h stores sealed)

    // ---- arrive ----
    if (tid == 0 && t < TSTEPS)
      asm volatile("red.release.gpu.global.add.u32 [%0], %1;" :: "l"(bar), "r"(1u));
  }

  // ---- exit: last CTA of bg resets counters for next graph replay ----
  __syncthreads();
  if (tid == 0) {
    __threadfence();
    if (atomicAdd(exitc, 1u) + 1u == 64u) {
      *bar = 0u;
      *exitc = 0u;
    }
  }
}

// ---------------- launch --------------------------------------------------------
extern "C" void kernel_launch(void* const* d_in, const int* in_sizes, int n_in,
                              void* d_out, int out_size) {
  const float* x   = (const float*)d_in[0];
  const float* W1  = (const float*)d_in[1];
  const float* U1m = (const float*)d_in[2];
  const float* b1  = (const float*)d_in[3];
  const float* W2  = (const float*)d_in[4];
  const float* U2m = (const float*)d_in[5];
  const float* b2  = (const float*)d_in[6];
  float* out = (float*)d_out;

  // per-CTA smem = 109312 B (2 CTAs/SM = 218624 B <= 228 KB)
  constexpr int SMEM = (256 * 16 + 384 * 8 + 256 * 36 + 128 * 36 +
                        8 * 16 * 33 + 8 * 8 * 33) * 4;  // 109312
  cudaFuncSetAttribute(lstm_fused, cudaFuncAttributeMaxDynamicSharedMemorySize, SMEM);

  // K1: xw1 = x @ W1 + b1
  gemm_xw1<<<dim3(1024 / 64, (BATCH * TSTEPS) / 64), 256>>>(x, W1, b1);

  // K2: fused persistent recurrence, 2 CTAs/SM
  lstm_fused<<<256, 256, SMEM>>>(U1m, b1, W2, U2m, b2, out);
}

// round 15
// speedup vs baseline: 1.1427x; 1.0242x over previous
#include <cuda_runtime.h>

#define BATCH  128
#define TSTEPS 512
#define FEAT   64
#define UN1    256
#define UN2    128

// packed fp32x2 FMA (Blackwell): two fp32 FMAs per instruction
#define FMA2(acc, a, b) \
  asm("fma.rn.f32x2 %0, %1, %2, %0;" : "+l"(acc) : "l"(a), "l"(b))
#define SPLAT2(dst, x) \
  asm("mov.b64 %0, {%1, %1};" : "=l"(dst) : "r"(__float_as_uint(x)))

#define CP_ASYNC16(saddr, gaddr) \
  asm volatile("cp.async.cg.shared.global [%0], [%1], 16;" :: "r"(saddr), "l"(gaddr))
#define CP_COMMIT() asm volatile("cp.async.commit_group;")
#define CP_WAIT0()  asm volatile("cp.async.wait_group 0;")

// ---------------- scratch ------------------------------------------------------
__device__ float g_hseq1[(size_t)(TSTEPS + 1) * UN1 * BATCH];  // [t][u][b], slot0 = 0
__device__ float g_hseq2[(size_t)(TSTEPS + 1) * UN2 * BATCH];  // [t][u][b], slot0 = 0
__device__ unsigned g_bar[4], g_exit[4];                       // per batch-group

// ---------------- fused persistent 2-layer LSTM --------------------------------
// 128 CTAs = 4 bg (32 batches) x 32 ug; 512 threads = 16 warps; 1 CTA/SM.
// Warp w: q = w>>1 (k-slice), half = w&1 (column half). 8 partial slices.
// __launch_bounds__(512, 1): allow up to 128 regs so ptxas can software-
// pipeline the LDS->SPLAT->FMA2 chains (R9 was capped at 64 regs, issue=33%).
__global__ void __launch_bounds__(512, 1)
lstm_fused(const float* __restrict__ x,
           const float* __restrict__ W1, const float* __restrict__ U1m,
           const float* __restrict__ b1,
           const float* __restrict__ W2, const float* __restrict__ U2m,
           const float* __restrict__ b2,
           float* __restrict__ out_last) {
  constexpr int SHS  = 36;   // sH / sH2e row stride
  constexpr int SXS  = 33;   // sX row stride
  constexpr int ZPS  = 33;   // sZp1: [q*32+col][bl]
  constexpr int ZP2S = 34;   // sZp2: [q*16+col][bl]

  extern __shared__ float smem[];
  float* sU1  = smem;                   // [256][32]
  float* sW1x = sU1 + 256 * 32;         // [64][32]
  float* sUW2 = sW1x + 64 * 32;         // [384][16]  W2 | U2
  float* sH   = sUW2 + 384 * 16;        // [256][SHS] h1_{t-1} [k][b]
  float* sH2e = sH + 256 * SHS;         // [128][SHS] h2_{t-2} [k][b]
  float* sX   = sH2e + 128 * SHS;       // [64][SXS]  x_t [f][b]
  float* sZp1 = sX + 64 * SXS;          // [8*32][ZPS]
  float* sZp2 = sZp1 + 8 * 32 * ZPS;    // [8*16][ZP2S]

  const int tid = threadIdx.x;
  const int bg  = blockIdx.x >> 5;
  const int ug  = blockIdx.x & 31;
  const int b0  = bg * 32;
  unsigned* bar   = &g_bar[bg];
  unsigned* exitc = &g_exit[bg];

  // ---- weight slices (once) ----
  for (int i = tid; i < 256 * 32; i += 512) {
    int k = i >> 5, cc = i & 31;
    sU1[i] = U1m[(size_t)k * 1024 + (cc >> 3) * 256 + ug * 8 + (cc & 7)];
  }
  for (int i = tid; i < 64 * 32; i += 512) {
    int k = i >> 5, cc = i & 31;
    sW1x[i] = W1[(size_t)k * 1024 + (cc >> 3) * 256 + ug * 8 + (cc & 7)];
  }
  for (int i = tid; i < 384 * 16; i += 512) {
    int k = i >> 4, c = i & 15;
    int col = (c >> 2) * 128 + ug * 4 + (c & 3);
    sUW2[i] = (k < 256) ? W2[(size_t)k * 512 + col]
                        : U2m[(size_t)(k - 256) * 512 + col];
  }

  // ---- thread mappings (compute) ----
  const int w    = tid >> 5;
  const int q    = w >> 1;           // k-slice 0..7
  const int half = w & 1;            // column half
  const int li   = tid & 31;
  const int tm   = li >> 2;          // rows 4*tm..+3
  const int tn   = li & 3;           // gate

  // epilogue mappings
  const int uu  = tid >> 5;          // L1 unit (valid for tid<256)
  const int bl  = tid & 31;
  const int b_g = b0 + bl;
  const int u_g = ug * 8 + (uu & 7);
  const int uu2  = (tid >> 5) & 3;   // L2 unit (tid<128)
  const int u_g2 = ug * 4 + uu2;

  float c1 = 0.f, c2 = 0.f;
  float b1g[4], b2g[4];
  if (tid < 256) {
#pragma unroll
    for (int g = 0; g < 4; g++) b1g[g] = b1[g * 256 + u_g];
  }
  if (tid < 128) {
#pragma unroll
    for (int g = 0; g < 4; g++) b2g[g] = b2[g * 128 + u_g2];
  }

  const unsigned sH_u   = (unsigned)__cvta_generic_to_shared(sH);
  const unsigned sH2e_u = (unsigned)__cvta_generic_to_shared(sH2e);

  // ---- init h_{-1}, first arrive, stage sX(t=0) ----
  if (tid < 256) g_hseq1[(size_t)u_g * BATCH + b_g] = 0.f;
  if (tid < 128) g_hseq2[(size_t)u_g2 * BATCH + b_g] = 0.f;
  __syncthreads();
  if (tid == 0)
    asm volatile("red.release.gpu.global.add.u32 [%0], %1;" :: "l"(bar), "r"(1u));
  {
    int bb = tid >> 4, f4 = (tid & 15) << 2;
    float4 v = *(const float4*)(x + (size_t)(b0 + bb) * TSTEPS * FEAT + f4);
    sX[(f4 + 0) * SXS + bb] = v.x;
    sX[(f4 + 1) * SXS + bb] = v.y;
    sX[(f4 + 2) * SXS + bb] = v.z;
    sX[(f4 + 3) * SXS + bb] = v.w;
  }

  for (int t = 0; t <= TSTEPS; t++) {
    // ---- wait: h1_{t-1} and h2_{t-2} sealed ----
    if (tid == 0) {
      const unsigned tgt = (unsigned)(t + 1) * 32u;
      unsigned v;
      do {
        asm volatile("ld.relaxed.gpu.global.u32 %0, [%1];" : "=r"(v) : "l"(bar));
      } while (v < tgt);
      asm volatile("ld.acquire.gpu.global.u32 %0, [%1];" : "=r"(v) : "l"(bar));
    }
    __syncthreads();                                   // S1

    // ---- issue async staging: sH = h1_{t-1}; sH2e = h2_{t-2} ----
    {
      const float* hp = g_hseq1 + (size_t)t * UN1 * BATCH + b0;
#pragma unroll
      for (int j = 0; j < 4; j++) {
        int i = tid + j * 512;
        int k = i >> 3, b4 = (i & 7) << 2;
        CP_ASYNC16(sH_u + (unsigned)(k * SHS + b4) * 4u,
                   hp + (size_t)k * BATCH + b4);
      }
    }
    if (t >= 1) {
      const float* hp = g_hseq2 + (size_t)(t - 1) * UN2 * BATCH + b0;
#pragma unroll
      for (int j = 0; j < 2; j++) {
        int i = tid + j * 512;
        int k = i >> 3, b4 = (i & 7) << 2;
        CP_ASYNC16(sH2e_u + (unsigned)(k * SHS + b4) * 4u,
                   hp + (size_t)k * BATCH + b4);
      }
    }
    CP_COMMIT();

    // ---- L1 x-part while copies fly ----
    unsigned long long acc[4][2];   // 4 rows x 4 L1 cols
    unsigned long long acc2[4];     // 4 rows x 2 L2 cols
#pragma unroll
    for (int r = 0; r < 4; r++) {
      acc[r][0] = 0ull; acc[r][1] = 0ull; acc2[r] = 0ull;
    }
#pragma unroll
    for (int kk = 0; kk < 8; kk++) {
      int k = q * 8 + kk;
      const float* ap = sX + k * SXS + 4 * tm;
      float a0 = ap[0], a1 = ap[1], a2 = ap[2], a3 = ap[3];
      ulonglong2 uA = *(const ulonglong2*)(sW1x + k * 32 + 8 * tn + 4 * half);
      unsigned long long s0, s1, s2, s3;
      SPLAT2(s0, a0); SPLAT2(s1, a1); SPLAT2(s2, a2); SPLAT2(s3, a3);
      FMA2(acc[0][0], s0, uA.x); FMA2(acc[0][1], s0, uA.y);
      FMA2(acc[1][0], s1, uA.x); FMA2(acc[1][1], s1, uA.y);
      FMA2(acc[2][0], s2, uA.x); FMA2(acc[2][1], s2, uA.y);
      FMA2(acc[3][0], s3, uA.x); FMA2(acc[3][1], s3, uA.y);
    }
    CP_WAIT0();
    __syncthreads();                                   // S2

    // ---- MERGED loop over sH: L1 U1-part + L2 W2-part ----
#pragma unroll 8
    for (int kk = 0; kk < 32; kk++) {
      int k = q * 32 + kk;
      float4 a = *(const float4*)(sH + k * SHS + 4 * tm);
      ulonglong2 uA = *(const ulonglong2*)(sU1 + k * 32 + 8 * tn + 4 * half);
      unsigned long long u2 = *(const unsigned long long*)(sUW2 + k * 16 + 4 * tn + 2 * half);
      unsigned long long s0, s1, s2, s3;
      SPLAT2(s0, a.x); SPLAT2(s1, a.y); SPLAT2(s2, a.z); SPLAT2(s3, a.w);
      FMA2(acc[0][0], s0, uA.x); FMA2(acc[0][1], s0, uA.y); FMA2(acc2[0], s0, u2);
      FMA2(acc[1][0], s1, uA.x); FMA2(acc[1][1], s1, uA.y); FMA2(acc2[1], s1, u2);
      FMA2(acc[2][0], s2, uA.x); FMA2(acc[2][1], s2, uA.y); FMA2(acc2[2], s2, u2);
      FMA2(acc[3][0], s3, uA.x); FMA2(acc[3][1], s3, uA.y); FMA2(acc2[3], s3, u2);
    }

    // ---- L2 U2-part over sH2e ----
#pragma unroll 16
    for (int kk = 0; kk < 16; kk++) {
      int k = q * 16 + kk;
      float4 a = *(const float4*)(sH2e + k * SHS + 4 * tm);
      unsigned long long u2 = *(const unsigned long long*)(sUW2 + (256 + k) * 16 + 4 * tn + 2 * half);
      unsigned long long s0, s1, s2, s3;
      SPLAT2(s0, a.x); SPLAT2(s1, a.y); SPLAT2(s2, a.z); SPLAT2(s3, a.w);
      FMA2(acc2[0], s0, u2);
      FMA2(acc2[1], s1, u2);
      FMA2(acc2[2], s2, u2);
      FMA2(acc2[3], s3, u2);
    }

    // ---- partial stores ([col][bl] layout; halves write disjoint cols) ----
#pragma unroll
    for (int r = 0; r < 4; r++) {
#pragma unroll
      for (int p = 0; p < 2; p++) {
        float lo = __uint_as_float((unsigned)(acc[r][p] & 0xffffffffu));
        float hi = __uint_as_float((unsigned)(acc[r][p] >> 32));
        sZp1[(q * 32 + 8 * tn + 4 * half + 2 * p)     * ZPS + 4 * tm + r] = lo;
        sZp1[(q * 32 + 8 * tn + 4 * half + 2 * p + 1) * ZPS + 4 * tm + r] = hi;
      }
      {
        float lo = __uint_as_float((unsigned)(acc2[r] & 0xffffffffu));
        float hi = __uint_as_float((unsigned)(acc2[r] >> 32));
        sZp2[(q * 16 + 4 * tn + 2 * half)     * ZP2S + 4 * tm + r] = lo;
        sZp2[(q * 16 + 4 * tn + 2 * half + 1) * ZP2S + 4 * tm + r] = hi;
      }
    }
    __syncthreads();                                   // S3

    // ---- L1 epilogue (threads 0..255) ----
    if (t < TSTEPS && tid < 256) {
      float z[4];
#pragma unroll
      for (int g = 0; g < 4; g++) {
        float s = b1g[g];
#pragma unroll
        for (int q2 = 0; q2 < 8; q2++)
          s += sZp1[(q2 * 32 + g * 8 + uu) * ZPS + bl];
        z[g] = s;
      }
      float ig = 1.f / (1.f + __expf(-z[0]));
      float fg = 1.f / (1.f + __expf(-z[1]));
      float gg = fmaxf(z[2], 0.f);
      float og = 1.f / (1.f + __expf(-z[3]));
      c1 = fg * c1 + ig * gg;
      float h = og * fmaxf(c1, 0.f);
      g_hseq1[(size_t)(t + 1) * UN1 * BATCH + (size_t)u_g * BATCH + b_g] = h;
    }
    // ---- L2 epilogue (threads 0..127; computes h2_{t-1}) ----
    if (t >= 1 && tid < 128) {
      float z[4];
#pragma unroll
      for (int g = 0; g < 4; g++) {
        float s = b2g[g];
#pragma unroll
        for (int q2 = 0; q2 < 8; q2++)
          s += sZp2[(q2 * 16 + g * 4 + uu2) * ZP2S + bl];
        z[g] = s;
      }
      float ig = 1.f / (1.f + __expf(-z[0]));
      float fg = 1.f / (1.f + __expf(-z[1]));
      float gg = fmaxf(z[2], 0.f);
      float og = 1.f / (1.f + __expf(-z[3]));
      c2 = fg * c2 + ig * gg;
      float h = og * fmaxf(c2, 0.f);
      if (t < TSTEPS)
        g_hseq2[(size_t)t * UN2 * BATCH + (size_t)u_g2 * BATCH + b_g] = h;
      else
        out_last[b_g * UN2 + u_g2] = h;
    }
    __syncthreads();                                   // S4 (h stores sealed)

    // ---- arrive, then stage sX for t+1 in the barrier shadow ----
    if (tid == 0 && t < TSTEPS)
      asm volatile("red.release.gpu.global.add.u32 [%0], %1;" :: "l"(bar), "r"(1u));
    if (t + 1 < TSTEPS) {
      int bb = tid >> 4, f4 = (tid & 15) << 2;
      float4 v = *(const float4*)(x + (size_t)(b0 + bb) * TSTEPS * FEAT
                                    + (size_t)(t + 1) * FEAT + f4);
      sX[(f4 + 0) * SXS + bb] = v.x;
      sX[(f4 + 1) * SXS + bb] = v.y;
      sX[(f4 + 2) * SXS + bb] = v.z;
      sX[(f4 + 3) * SXS + bb] = v.w;
    }
  }

  // ---- exit: last CTA of bg resets counters for next graph replay ----
  __syncthreads();
  if (tid == 0) {
    __threadfence();
    if (atomicAdd(exitc, 1u) + 1u == 32u) {
      *bar = 0u;
      *exitc = 0u;
    }
  }
}

// ---------------- launch --------------------------------------------------------
extern "C" void kernel_launch(void* const* d_in, const int* in_sizes, int n_in,
                              void* d_out, int out_size) {
  const float* x   = (const float*)d_in[0];
  const float* W1  = (const float*)d_in[1];
  const float* U1m = (const float*)d_in[2];
  const float* b1  = (const float*)d_in[3];
  const float* W2  = (const float*)d_in[4];
  const float* U2m = (const float*)d_in[5];
  const float* b2  = (const float*)d_in[6];
  float* out = (float*)d_out;

  constexpr int SMEM = (256 * 32 + 64 * 32 + 384 * 16 + 256 * 36 + 128 * 36 +
                        64 * 33 + 8 * 32 * 33 + 8 * 16 * 34) * 4;   // 180480 B
  cudaFuncSetAttribute(lstm_fused, cudaFuncAttributeMaxDynamicSharedMemorySize, SMEM);

  lstm_fused<<<128, 512, SMEM>>>(x, W1, U1m, b1, W2, U2m, b2, out);
}